// round 13
// baseline (speedup 1.0000x reference)
#include <cuda_runtime.h>
#include <cuda_bf16.h>
#include <math.h>
#include <stdint.h>

#define NN 20000
#define NE 320000
#define DH 128
#define DIN 64
#define NT 20
#define LNEPS 1e-5f

// ---------------- scratch (device globals: no allocation allowed) ----------
__device__ float g_dt;
__device__ float g_epi;

__device__ float d_g   [NN * DH];
__device__ float d_bufA[NN * DH];
__device__ float d_bufB[NN * DH];
__device__ float d_y   [NN * DH];
__device__ float d_acc [NN * DH];
__device__ float d_h   [NN * DH];

__device__ float d_dis[NN];
__device__ int   d_counts[NN];
__device__ int   d_off[NN + 1];
__device__ int   d_cursor[NN];
__device__ int   d_csr_src[NE];

// pre-split bf16 hi/lo weights, packed 2 consecutive k per uint32.
#define WP_I    0
#define WP_GCN  4096
#define WP_GATE 28672
#define WP_WO   45056
#define WP_TOT  53248
#define LAYER_P 8192
__device__ uint32_t d_whi[WP_TOT];
__device__ uint32_t d_wlo[WP_TOT];

// ---------------- bf16 split helpers ----------------------------------------
__device__ __forceinline__ uint32_t pack2(__nv_bfloat16 a, __nv_bfloat16 b) {
    uint16_t ua = __bfloat16_as_ushort(a), ub = __bfloat16_as_ushort(b);
    return (uint32_t)ua | ((uint32_t)ub << 16);
}
__device__ __forceinline__ void split_pack(float x, float y, uint32_t& hi, uint32_t& lo) {
    __nv_bfloat16 bx = __float2bfloat16(x);
    __nv_bfloat16 by = __float2bfloat16(y);
    float rx = x - __bfloat162float(bx);
    float ry = y - __bfloat162float(by);
    hi = pack2(bx, by);
    lo = pack2(__float2bfloat16(rx), __float2bfloat16(ry));
}
__device__ __forceinline__ void mma_bf16(float c[4], const uint32_t a[4], const uint32_t b[2]) {
    asm volatile(
        "mma.sync.aligned.m16n8k16.row.col.f32.bf16.bf16.f32 "
        "{%0,%1,%2,%3},{%4,%5,%6,%7},{%8,%9},{%0,%1,%2,%3};"
        : "+f"(c[0]), "+f"(c[1]), "+f"(c[2]), "+f"(c[3])
        : "r"(a[0]), "r"(a[1]), "r"(a[2]), "r"(a[3]), "r"(b[0]), "r"(b[1]));
}

// ---------------- cp.async helpers ------------------------------------------
__device__ __forceinline__ uint32_t smem_u32(const void* p) {
    uint32_t r;
    asm("{ .reg .u64 t; cvta.to.shared.u64 t, %1; cvt.u32.u64 %0, t; }"
        : "=r"(r) : "l"(p));
    return r;
}
__device__ __forceinline__ void cp16(uint32_t saddr, const void* gaddr) {
    asm volatile("cp.async.ca.shared.global [%0], [%1], 16;" :: "r"(saddr), "l"(gaddr));
}
__device__ __forceinline__ void cp_commit() {
    asm volatile("cp.async.commit_group;");
}
template <int N>
__device__ __forceinline__ void cp_wait() {
    asm volatile("cp.async.wait_group %0;" :: "n"(N));
}

#define SA_STRIDE 20
#define SW_STRIDE 132

// A single-buffered (hi/lo planes); W double-buffered for cp.async prefetch.
struct SmemC {
    uint32_t a[2][64 * SA_STRIDE];        // 10240 B
    uint32_t w[2][2][16 * SW_STRIDE];     // 33792 B  [buf][hi/lo]
};

// ---------------- prologue kernels -----------------------------------------
__global__ void k_pre0(const float* __restrict__ log_depth,
                       const float* __restrict__ meth,
                       const float* __restrict__ hist) {
    int i = blockIdx.x * blockDim.x + threadIdx.x;
    if (i < NN) d_counts[i] = 0;
    if (blockIdx.x == 0 && threadIdx.x < 32) {
        int t = threadIdx.x;
        float v = 0.f;
        for (int j = t; j < 128; j += 32) v += 1.f / (1.f + expf(-meth[j]));
        for (int o = 16; o > 0; o >>= 1) v += __shfl_xor_sync(0xffffffff, v, o);
        if (t == 0) {
            float ms = v / 128.f;
            float h0 = 1.f / (1.f + expf(-hist[0]));
            float h1 = 1.f / (1.f + expf(-hist[1]));
            float h2 = 1.f / (1.f + expf(-hist[2]));
            float h3 = 1.f / (1.f + expf(-hist[3]));
            float act = 0.5f * (h0 + h2);
            float rep = 0.5f * (h1 + h3);
            float acc = fminf(fmaxf(act - rep + 0.5f, 0.f), 1.f);
            g_epi = acc * (1.f - ms);
            float d = expf(log_depth[0]);
            d = fminf(fmaxf(d, 0.1f), 3.0f);
            g_dt = d / (float)(NT - 1);
        }
    }
}

__global__ void k_count(const int* __restrict__ ei) {
    int e = blockIdx.x * blockDim.x + threadIdx.x;
    if (e < NE) atomicAdd(&d_counts[ei[NE + e]], 1);
}

__global__ void k_scan() {
    __shared__ int sm[1024];
    int t = threadIdx.x;
    const int CH = (NN + 1023) / 1024;
    int beg = t * CH;
    int end = min(NN, beg + CH);
    int s = 0;
    for (int i = beg; i < end; i++) s += d_counts[i];
    sm[t] = s;
    __syncthreads();
    for (int o = 1; o < 1024; o <<= 1) {
        int v = (t >= o) ? sm[t - o] : 0;
        __syncthreads();
        sm[t] += v;
        __syncthreads();
    }
    int run = sm[t] - s;
    for (int i = beg; i < end; i++) {
        int c = d_counts[i];
        d_off[i] = run;
        d_cursor[i] = run;
        d_dis[i] = (c > 0) ? rsqrtf((float)c) : 0.f;
        run += c;
    }
    if (t == 1023) d_off[NN] = sm[1023];
}

__global__ void k_fill(const int* __restrict__ ei) {
    int e = blockIdx.x * blockDim.x + threadIdx.x;
    if (e < NE) {
        int c = ei[NE + e];
        int p = atomicAdd(&d_cursor[c], 1);
        d_csr_src[p] = ei[e];
    }
}

__global__ void k_split_w(const float* __restrict__ Wi, const float* __restrict__ gcn,
                          const float* __restrict__ gate, const float* __restrict__ Wo) {
    int i = blockIdx.x * blockDim.x + threadIdx.x;
    if (i >= WP_TOT) return;
    const float* src;
    int p;
    if (i < WP_GCN)       { src = Wi;   p = i - WP_I; }
    else if (i < WP_GATE) { src = gcn;  p = i - WP_GCN; }
    else if (i < WP_WO)   { src = gate; p = i - WP_GATE; }
    else                  { src = Wo;   p = i - WP_WO; }
    int c = p & 127;
    int k2 = p >> 7;
    float f0 = src[(2 * k2) * DH + c];
    float f1 = src[(2 * k2 + 1) * DH + c];
    uint32_t hi, lo;
    split_pack(f0, f1, hi, lo);
    d_whi[i] = hi;
    d_wlo[i] = lo;
}

// ---------------- GEMM building blocks --------------------------------------
// async-stage one 16-pair-row x 128-col W chunk into buffer `buf`
__device__ __forceinline__ void stage_w_async(SmemC& s,
        const uint32_t* __restrict__ whi, const uint32_t* __restrict__ wlo,
        int kp0, int buf, int tid) {
#pragma unroll
    for (int it = 0; it < 2; it++) {
        int i = tid + it * 256;
        int kr = i >> 5, cq = i & 31;
        int gi = (kp0 + kr) * DH + cq * 4;
        cp16(smem_u32(&s.w[buf][0][kr * SW_STRIDE + cq * 4]), &whi[gi]);
        cp16(smem_u32(&s.w[buf][1][kr * SW_STRIDE + cq * 4]), &wlo[gi]);
    }
    cp_commit();
}

__device__ __forceinline__ void mma_phase(SmemC& s, int buf, float (&acc)[2][4][4],
                                          int wm, int wn, int grp, int qid) {
#pragma unroll
    for (int kk2 = 0; kk2 < 16; kk2 += 8) {
        uint32_t ah[2][4], al[2][4], bh[4][2], bl[4][2];
#pragma unroll
        for (int mi = 0; mi < 2; mi++) {
            int r = wm * 32 + mi * 16 + grp;
            int i0 = r * SA_STRIDE + kk2 + qid;
            int i1 = (r + 8) * SA_STRIDE + kk2 + qid;
            ah[mi][0] = s.a[0][i0];     ah[mi][1] = s.a[0][i1];
            ah[mi][2] = s.a[0][i0 + 4]; ah[mi][3] = s.a[0][i1 + 4];
            al[mi][0] = s.a[1][i0];     al[mi][1] = s.a[1][i1];
            al[mi][2] = s.a[1][i0 + 4]; al[mi][3] = s.a[1][i1 + 4];
        }
#pragma unroll
        for (int ni = 0; ni < 4; ni++) {
            int n = wn * 32 + ni * 8 + grp;
            bh[ni][0] = s.w[buf][0][(kk2 + qid) * SW_STRIDE + n];
            bh[ni][1] = s.w[buf][0][(kk2 + qid + 4) * SW_STRIDE + n];
            bl[ni][0] = s.w[buf][1][(kk2 + qid) * SW_STRIDE + n];
            bl[ni][1] = s.w[buf][1][(kk2 + qid + 4) * SW_STRIDE + n];
        }
#pragma unroll
        for (int mi = 0; mi < 2; mi++)
#pragma unroll
            for (int ni = 0; ni < 4; ni++) {
                mma_bf16(acc[mi][ni], al[mi], bh[ni]);
                mma_bf16(acc[mi][ni], ah[mi], bl[ni]);
                mma_bf16(acc[mi][ni], ah[mi], bh[ni]);
            }
    }
}

// ---------------- split-bf16 GEMM (cp.async W prefetch, 3 CTA/SM) -----------
// C[M x 128] = A[M x K] @ W[K x 128]. EPI 0: +bias  EPI 1: *dis[row]
template <int K, int EPI>
__global__ __launch_bounds__(256, 3) void k_gemm_tc(
        const float* __restrict__ A,
        const uint32_t* __restrict__ whi, const uint32_t* __restrict__ wlo,
        const float* __restrict__ bias, float* __restrict__ C, int M) {
    __shared__ SmemC s;
    const int NC = K / 32;
    int tid = threadIdx.x;
    int warp = tid >> 5, lane = tid & 31;
    int grp = lane >> 2, qid = lane & 3;
    int wm = warp >> 2, wn = warp & 3;
    int r0 = blockIdx.x * 64;

    float acc[2][4][4];
#pragma unroll
    for (int mi = 0; mi < 2; mi++)
#pragma unroll
        for (int ni = 0; ni < 4; ni++)
#pragma unroll
            for (int j = 0; j < 4; j++) acc[mi][ni][j] = 0.f;

    stage_w_async(s, whi, wlo, 0, 0, tid);

    for (int c = 0; c < NC; c++) {
        int k0 = c * 32;
#pragma unroll
        for (int it = 0; it < 2; it++) {
            int i = tid + it * 256;
            int row = i >> 3, q = i & 7;
            int gr = r0 + row;
            float4 v = make_float4(0.f, 0.f, 0.f, 0.f);
            if (gr < M) v = *(const float4*)&A[gr * K + k0 + q * 4];
            uint32_t h0, l0, h1, l1;
            split_pack(v.x, v.y, h0, l0);
            split_pack(v.z, v.w, h1, l1);
            int base = row * SA_STRIDE + q * 2;
            s.a[0][base] = h0; s.a[0][base + 1] = h1;
            s.a[1][base] = l0; s.a[1][base + 1] = l1;
        }
        if (c + 1 < NC) {
            stage_w_async(s, whi, wlo, (c + 1) * 16, (c + 1) & 1, tid);
            cp_wait<1>();
        } else {
            cp_wait<0>();
        }
        __syncthreads();
        mma_phase(s, c & 1, acc, wm, wn, grp, qid);
        __syncthreads();
    }

#pragma unroll
    for (int mi = 0; mi < 2; mi++) {
        int row = r0 + wm * 32 + mi * 16 + grp;
#pragma unroll
        for (int half = 0; half < 2; half++) {
            int r = row + half * 8;
            if (r < M) {
                float sc = (EPI == 1) ? d_dis[r] : 0.f;
#pragma unroll
                for (int ni = 0; ni < 4; ni++) {
                    int col = wn * 32 + ni * 8 + 2 * qid;
                    float v0 = acc[mi][ni][half * 2 + 0];
                    float v1 = acc[mi][ni][half * 2 + 1];
                    if (EPI == 0) { v0 += bias[col]; v1 += bias[col + 1]; }
                    else          { v0 *= sc;        v1 *= sc; }
                    C[r * DH + col] = v0;
                    C[r * DH + col + 1] = v1;
                }
            }
        }
    }
}

// gate GEMM (K=256, A = concat(hc, hn)), cp.async W prefetch, 3 CTA/SM.
// FUSE 0: hc = g*hn + (1-g)*hc
// FUSE 1: kv = tanh(blend) + rw*yin; yout = h + ycoef*dt*kv;
//         acc = first ? kv : acc + acoef*kv
// FUSE 2: kv = tanh(blend) + rw*yin; h += dt/6*(acc + kv)
template <int FUSE>
__global__ __launch_bounds__(256, 3) void k_gate_tc(
        float* __restrict__ hc, const float* __restrict__ hn,
        const uint32_t* __restrict__ whi, const uint32_t* __restrict__ wlo,
        const float* __restrict__ gb, int M,
        const float* yin, float* yout,
        float* h, float* acc_buf,
        const float* __restrict__ res_w,
        float ycoef, float acoef, int first) {
    __shared__ SmemC s;
    const int NC = 8;
    int tid = threadIdx.x;
    int warp = tid >> 5, lane = tid & 31;
    int grp = lane >> 2, qid = lane & 3;
    int wm = warp >> 2, wn = warp & 3;
    int r0 = blockIdx.x * 64;

    float acc[2][4][4];
#pragma unroll
    for (int mi = 0; mi < 2; mi++)
#pragma unroll
        for (int ni = 0; ni < 4; ni++)
#pragma unroll
            for (int j = 0; j < 4; j++) acc[mi][ni][j] = 0.f;

    stage_w_async(s, whi, wlo, 0, 0, tid);

    for (int c = 0; c < NC; c++) {
        int k0 = c * 32;
#pragma unroll
        for (int it = 0; it < 2; it++) {
            int i = tid + it * 256;
            int row = i >> 3, q = i & 7;
            int gr = r0 + row;
            int cc = k0 + q * 4;
            float4 v = make_float4(0.f, 0.f, 0.f, 0.f);
            if (gr < M)
                v = (cc < DH) ? *(const float4*)&hc[gr * DH + cc]
                              : *(const float4*)&hn[gr * DH + (cc - DH)];
            uint32_t h0, l0, h1, l1;
            split_pack(v.x, v.y, h0, l0);
            split_pack(v.z, v.w, h1, l1);
            int base = row * SA_STRIDE + q * 2;
            s.a[0][base] = h0; s.a[0][base + 1] = h1;
            s.a[1][base] = l0; s.a[1][base + 1] = l1;
        }
        if (c + 1 < NC) {
            stage_w_async(s, whi, wlo, (c + 1) * 16, (c + 1) & 1, tid);
            cp_wait<1>();
        } else {
            cp_wait<0>();
        }
        __syncthreads();
        mma_phase(s, c & 1, acc, wm, wn, grp, qid);
        __syncthreads();
    }
    // all block-wide reads of hc complete (last __syncthreads above)
    float rw = (FUSE != 0) ? res_w[0] : 0.f;
    float dt = (FUSE != 0) ? g_dt : 0.f;
#pragma unroll
    for (int mi = 0; mi < 2; mi++) {
        int row = r0 + wm * 32 + mi * 16 + grp;
#pragma unroll
        for (int half = 0; half < 2; half++) {
            int r = row + half * 8;
            if (r < M) {
#pragma unroll
                for (int ni = 0; ni < 4; ni++) {
                    int col = wn * 32 + ni * 8 + 2 * qid;
#pragma unroll
                    for (int j = 0; j < 2; j++) {
                        int c2 = col + j;
                        float z = acc[mi][ni][half * 2 + j] + gb[c2];
                        float gt = 1.f / (1.f + expf(-z));
                        int idx = r * DH + c2;
                        float blend = gt * hn[idx] + (1.f - gt) * hc[idx];
                        if (FUSE == 0) {
                            hc[idx] = blend;
                        } else if (FUSE == 1) {
                            float kv = tanhf(blend) + rw * yin[idx];
                            float yv = h[idx] + ycoef * dt * kv;
                            float av = first ? kv : acc_buf[idx] + acoef * kv;
                            yout[idx] = yv;
                            acc_buf[idx] = av;
                        } else {
                            float kv = tanhf(blend) + rw * yin[idx];
                            h[idx] += (dt * (1.f / 6.f)) * (acc_buf[idx] + kv);
                        }
                    }
                }
            }
        }
    }
}

// ---------------- aggregation + LayerNorm (warp per node, 4-way MLP) -------
__global__ void k_agg_ln(const float* __restrict__ g, const float* __restrict__ b,
                         const float* __restrict__ lg, const float* __restrict__ lb,
                         float* __restrict__ out) {
    int warp = threadIdx.x >> 5, lane = threadIdx.x & 31;
    int n = blockIdx.x * 8 + warp;
    if (n >= NN) return;
    int beg = d_off[n], end = d_off[n + 1];
    int c4 = lane * 4;
    float4 a0 = make_float4(0.f, 0.f, 0.f, 0.f);
    float4 a1 = make_float4(0.f, 0.f, 0.f, 0.f);
    float4 a2 = make_float4(0.f, 0.f, 0.f, 0.f);
    float4 a3 = make_float4(0.f, 0.f, 0.f, 0.f);
    int e = beg;
    for (; e + 3 < end; e += 4) {
        int s0 = d_csr_src[e], s1 = d_csr_src[e + 1];
        int s2 = d_csr_src[e + 2], s3 = d_csr_src[e + 3];
        float4 v0 = *(const float4*)&g[s0 * DH + c4];
        float4 v1 = *(const float4*)&g[s1 * DH + c4];
        float4 v2 = *(const float4*)&g[s2 * DH + c4];
        float4 v3 = *(const float4*)&g[s3 * DH + c4];
        a0.x += v0.x; a0.y += v0.y; a0.z += v0.z; a0.w += v0.w;
        a1.x += v1.x; a1.y += v1.y; a1.z += v1.z; a1.w += v1.w;
        a2.x += v2.x; a2.y += v2.y; a2.z += v2.z; a2.w += v2.w;
        a3.x += v3.x; a3.y += v3.y; a3.z += v3.z; a3.w += v3.w;
    }
    for (; e < end; e++) {
        int s0 = d_csr_src[e];
        float4 v0 = *(const float4*)&g[s0 * DH + c4];
        a0.x += v0.x; a0.y += v0.y; a0.z += v0.z; a0.w += v0.w;
    }
    float dis = d_dis[n];
    float4 b4 = *(const float4*)&b[c4];
    float sx = (a0.x + a1.x + a2.x + a3.x) * dis + b4.x;
    float sy = (a0.y + a1.y + a2.y + a3.y) * dis + b4.y;
    float sz = (a0.z + a1.z + a2.z + a3.z) * dis + b4.z;
    float sw = (a0.w + a1.w + a2.w + a3.w) * dis + b4.w;
    float s = sx + sy + sz + sw;
    for (int o = 16; o > 0; o >>= 1) s += __shfl_xor_sync(0xffffffff, s, o);
    float mu = s * (1.f / 128.f);
    float dx = sx - mu, dy = sy - mu, dz = sz - mu, dw = sw - mu;
    float q = dx * dx + dy * dy + dz * dz + dw * dw;
    for (int o = 16; o > 0; o >>= 1) q += __shfl_xor_sync(0xffffffff, q, o);
    float rs = rsqrtf(q * (1.f / 128.f) + LNEPS);
    float4 lg4 = *(const float4*)&lg[c4];
    float4 lb4 = *(const float4*)&lb[c4];
    float4 o4;
    o4.x = dx * rs * lg4.x + lb4.x;
    o4.y = dy * rs * lg4.y + lb4.y;
    o4.z = dz * rs * lg4.z + lb4.z;
    o4.w = dw * rs * lg4.w + lb4.w;
    *(float4*)&out[n * DH + c4] = o4;
}

// row LayerNorm (warp per row). MODE 1: + relu + *g_epi
template <int MODE>
__global__ void k_ln_rows(const float* __restrict__ in, const float* __restrict__ lg,
                          const float* __restrict__ lb, float* __restrict__ out, int M) {
    int warp = threadIdx.x >> 5, lane = threadIdx.x & 31;
    int r = blockIdx.x * 4 + warp;
    if (r >= M) return;
    float4 v = *(const float4*)&in[r * DH + lane * 4];
    float s = v.x + v.y + v.z + v.w;
    for (int o = 16; o > 0; o >>= 1) s += __shfl_xor_sync(0xffffffff, s, o);
    float mu = s * (1.f / 128.f);
    float dx = v.x - mu, dy = v.y - mu, dz = v.z - mu, dw = v.w - mu;
    float q = dx * dx + dy * dy + dz * dz + dw * dw;
    for (int o = 16; o > 0; o >>= 1) q += __shfl_xor_sync(0xffffffff, q, o);
    float rs = rsqrtf(q * (1.f / 128.f) + LNEPS);
    float4 o4;
    float e = g_epi;
    int c = lane * 4;
    o4.x = dx * rs * lg[c + 0] + lb[c + 0];
    o4.y = dy * rs * lg[c + 1] + lb[c + 1];
    o4.z = dz * rs * lg[c + 2] + lb[c + 2];
    o4.w = dw * rs * lg[c + 3] + lb[c + 3];
    if (MODE == 1) {
        o4.x = fmaxf(o4.x, 0.f) * e;
        o4.y = fmaxf(o4.y, 0.f) * e;
        o4.z = fmaxf(o4.z, 0.f) * e;
        o4.w = fmaxf(o4.w, 0.f) * e;
    }
    *(float4*)&out[r * DH + lane * 4] = o4;
}

// ---------------- output ---------------------------------------------------
__global__ void k_zero_out(float* out) {
    if (threadIdx.x < DH) out[threadIdx.x] = 0.f;
}

__global__ void k_colmean(const float* __restrict__ a, float* __restrict__ out) {
    int j = threadIdx.x;
    int r0 = blockIdx.x * 128;
    int r1 = min(NN, r0 + 128);
    float s = 0.f;
    for (int r = r0; r < r1; r++) s += a[r * DH + j];
    atomicAdd(&out[j], s * (1.f / (float)NN));
}

// ---------------- host orchestration ---------------------------------------
extern "C" void kernel_launch(void* const* d_in, const int* in_sizes, int n_in,
                              void* d_out, int out_size) {
    const float* x        = (const float*)d_in[0];
    const int*   ei       = (const int*)  d_in[1];
    const float* Wi       = (const float*)d_in[2];
    const float* bi       = (const float*)d_in[3];
    const float* ln_in_g  = (const float*)d_in[4];
    const float* ln_in_b  = (const float*)d_in[5];
    const float* meth     = (const float*)d_in[6];
    const float* hist     = (const float*)d_in[7];
    const float* gcn_w    = (const float*)d_in[8];
    const float* gcn_b    = (const float*)d_in[9];
    const float* ln_g     = (const float*)d_in[10];
    const float* ln_b     = (const float*)d_in[11];
    const float* gate_w   = (const float*)d_in[12];
    const float* gate_b   = (const float*)d_in[13];
    const float* res_w    = (const float*)d_in[14];
    const float* log_depth= (const float*)d_in[15];
    const float* Wo       = (const float*)d_in[16];
    const float* bo       = (const float*)d_in[17];
    const float* ln_out_g = (const float*)d_in[18];
    const float* ln_out_b = (const float*)d_in[19];
    float* out = (float*)d_out;

    float *p_g, *p_A, *p_B, *p_y, *p_acc, *p_h;
    uint32_t *p_whi, *p_wlo;
    cudaGetSymbolAddress((void**)&p_g,   d_g);
    cudaGetSymbolAddress((void**)&p_A,   d_bufA);
    cudaGetSymbolAddress((void**)&p_B,   d_bufB);
    cudaGetSymbolAddress((void**)&p_y,   d_y);
    cudaGetSymbolAddress((void**)&p_acc, d_acc);
    cudaGetSymbolAddress((void**)&p_h,   d_h);
    cudaGetSymbolAddress((void**)&p_whi, d_whi);
    cudaGetSymbolAddress((void**)&p_wlo, d_wlo);

    const int GEMM_GRID = (NN + 63) / 64;   // 313
    const int AGG_GRID  = (NN + 7) / 8;     // 2500
    const int LN_GRID   = (NN + 3) / 4;     // 5000

    // prologue — launch index 3 = input-projection GEMM (ncu capture target)
    k_pre0<<<(NN + 255) / 256, 256>>>(log_depth, meth, hist);             // 0
    k_split_w<<<(WP_TOT + 255) / 256, 256>>>(Wi, gcn_w, gate_w, Wo);      // 1
    k_count<<<(NE + 255) / 256, 256>>>(ei);                               // 2
    k_gemm_tc<DIN, 0><<<GEMM_GRID, 256>>>(x, p_whi + WP_I, p_wlo + WP_I,
                                          bi, p_g, NN);                   // 3
    k_scan<<<1, 1024>>>();                                                // 4
    k_fill<<<(NE + 255) / 256, 256>>>(ei);                                // 5
    k_ln_rows<1><<<LN_GRID, 128>>>(p_g, ln_in_g, ln_in_b, p_h, NN);       // 6

    auto f_eval = [&](const float* in, int mode, float ycoef, float acoef, int first) {
        const uint32_t* g0h = p_whi + WP_GCN;
        const uint32_t* g0l = p_wlo + WP_GCN;
        // layer 0
        k_gemm_tc<DH, 1><<<GEMM_GRID, 256>>>(in, g0h, g0l, nullptr, p_g, NN);
        k_agg_ln<<<AGG_GRID, 256>>>(p_g, gcn_b, ln_g, ln_b, p_A);
        // layer 1 + plain gate
        k_gemm_tc<DH, 1><<<GEMM_GRID, 256>>>(p_A, g0h + LAYER_P, g0l + LAYER_P,
                                             nullptr, p_g, NN);
        k_agg_ln<<<AGG_GRID, 256>>>(p_g, gcn_b + DH, ln_g + DH, ln_b + DH, p_B);
        k_gate_tc<0><<<GEMM_GRID, 256>>>(p_A, p_B, p_whi + WP_GATE, p_wlo + WP_GATE,
                                         gate_b, NN, nullptr, nullptr, nullptr,
                                         nullptr, nullptr, 0.f, 0.f, 0);
        // layer 2 + gate fused with tanh/residual + RK update
        k_gemm_tc<DH, 1><<<GEMM_GRID, 256>>>(p_A, g0h + 2 * LAYER_P, g0l + 2 * LAYER_P,
                                             nullptr, p_g, NN);
        k_agg_ln<<<AGG_GRID, 256>>>(p_g, gcn_b + 2 * DH, ln_g + 2 * DH, ln_b + 2 * DH, p_B);
        if (mode == 1)
            k_gate_tc<1><<<GEMM_GRID, 256>>>(p_A, p_B, p_whi + WP_GATE, p_wlo + WP_GATE,
                                             gate_b, NN, in, p_y, p_h, p_acc,
                                             res_w, ycoef, acoef, first);
        else
            k_gate_tc<2><<<GEMM_GRID, 256>>>(p_A, p_B, p_whi + WP_GATE, p_wlo + WP_GATE,
                                             gate_b, NN, in, nullptr, p_h, p_acc,
                                             res_w, 0.f, 0.f, 0);
    };

    for (int step = 0; step < NT - 1; step++) {
        f_eval(p_h, 1, 0.5f, 1.f, 1);   // k1
        f_eval(p_y, 1, 0.5f, 2.f, 0);   // k2
        f_eval(p_y, 1, 1.0f, 2.f, 0);   // k3
        f_eval(p_y, 2, 0.f, 0.f, 0);    // k4
    }

    // output projection + LN + global mean pool
    k_gemm_tc<DH, 0><<<GEMM_GRID, 256>>>(p_h, p_whi + WP_WO, p_wlo + WP_WO,
                                         bo, p_g, NN);
    k_ln_rows<0><<<LN_GRID, 128>>>(p_g, ln_out_g, ln_out_b, p_B, NN);
    k_zero_out<<<1, 128>>>(out);
    k_colmean<<<(NN + 127) / 128, 128>>>(p_B, out);
}

// round 14
// speedup vs baseline: 1.0338x; 1.0338x over previous
#include <cuda_runtime.h>
#include <cuda_bf16.h>
#include <cuda_fp16.h>
#include <math.h>
#include <stdint.h>

#define NN 20000
#define NE 320000
#define DH 128
#define DIN 64
#define NT 20
#define LNEPS 1e-5f

// ---------------- scratch (device globals: no allocation allowed) ----------
__device__ float g_dt;
__device__ float g_epi;

__device__ float d_g   [NN * DH];   // agg output / projection scratch
__device__ float d_bufA[NN * DH];   // hc
__device__ float d_bufB[NN * DH];   // hn
__device__ float d_y   [NN * DH];
__device__ float d_acc [NN * DH];
__device__ float d_h   [NN * DH];
__device__ __half d_t16[NN * DH];   // fp16 dis-scaled activations (gather source)

__device__ float d_dis[NN];
__device__ int   d_counts[NN];
__device__ int   d_off[NN + 1];
__device__ int   d_cursor[NN];
__device__ int   d_csr_src[NE];

// pre-split bf16 hi/lo weights, packed 2 consecutive k per uint32.
#define WP_I    0
#define WP_GCN  4096
#define WP_GATE 28672
#define WP_WO   45056
#define WP_TOT  53248
#define LAYER_P 8192
__device__ uint32_t d_whi[WP_TOT];
__device__ uint32_t d_wlo[WP_TOT];

// ---------------- bf16 split helpers ----------------------------------------
__device__ __forceinline__ uint32_t pack2(__nv_bfloat16 a, __nv_bfloat16 b) {
    uint16_t ua = __bfloat16_as_ushort(a), ub = __bfloat16_as_ushort(b);
    return (uint32_t)ua | ((uint32_t)ub << 16);
}
__device__ __forceinline__ void split_pack(float x, float y, uint32_t& hi, uint32_t& lo) {
    __nv_bfloat16 bx = __float2bfloat16(x);
    __nv_bfloat16 by = __float2bfloat16(y);
    float rx = x - __bfloat162float(bx);
    float ry = y - __bfloat162float(by);
    hi = pack2(bx, by);
    lo = pack2(__float2bfloat16(rx), __float2bfloat16(ry));
}
__device__ __forceinline__ void mma_bf16(float c[4], const uint32_t a[4], const uint32_t b[2]) {
    asm volatile(
        "mma.sync.aligned.m16n8k16.row.col.f32.bf16.bf16.f32 "
        "{%0,%1,%2,%3},{%4,%5,%6,%7},{%8,%9},{%0,%1,%2,%3};"
        : "+f"(c[0]), "+f"(c[1]), "+f"(c[2]), "+f"(c[3])
        : "r"(a[0]), "r"(a[1]), "r"(a[2]), "r"(a[3]), "r"(b[0]), "r"(b[1]));
}

// ---------------- cp.async helpers ------------------------------------------
__device__ __forceinline__ uint32_t smem_u32(const void* p) {
    uint32_t r;
    asm("{ .reg .u64 t; cvta.to.shared.u64 t, %1; cvt.u32.u64 %0, t; }"
        : "=r"(r) : "l"(p));
    return r;
}
__device__ __forceinline__ void cp16(uint32_t saddr, const void* gaddr) {
    asm volatile("cp.async.ca.shared.global [%0], [%1], 16;" :: "r"(saddr), "l"(gaddr));
}
__device__ __forceinline__ void cp_commit() {
    asm volatile("cp.async.commit_group;");
}
template <int N>
__device__ __forceinline__ void cp_wait() {
    asm volatile("cp.async.wait_group %0;" :: "n"(N));
}

#define SA_STRIDE 20
#define SW_STRIDE 132

// A single-buffered (hi/lo planes); W double-buffered for cp.async prefetch.
// s.w is reused as a 64x132 fp32 tile for the LN epilogue (exact size match).
struct SmemC {
    uint32_t a[2][64 * SA_STRIDE];        // 10240 B
    uint32_t w[2][2][16 * SW_STRIDE];     // 33792 B  [buf][hi/lo]
};

// ---------------- prologue kernels -----------------------------------------
__global__ void k_pre0(const float* __restrict__ log_depth,
                       const float* __restrict__ meth,
                       const float* __restrict__ hist) {
    int i = blockIdx.x * blockDim.x + threadIdx.x;
    if (i < NN) d_counts[i] = 0;
    if (blockIdx.x == 0 && threadIdx.x < 32) {
        int t = threadIdx.x;
        float v = 0.f;
        for (int j = t; j < 128; j += 32) v += 1.f / (1.f + expf(-meth[j]));
        for (int o = 16; o > 0; o >>= 1) v += __shfl_xor_sync(0xffffffff, v, o);
        if (t == 0) {
            float ms = v / 128.f;
            float h0 = 1.f / (1.f + expf(-hist[0]));
            float h1 = 1.f / (1.f + expf(-hist[1]));
            float h2 = 1.f / (1.f + expf(-hist[2]));
            float h3 = 1.f / (1.f + expf(-hist[3]));
            float act = 0.5f * (h0 + h2);
            float rep = 0.5f * (h1 + h3);
            float acc = fminf(fmaxf(act - rep + 0.5f, 0.f), 1.f);
            g_epi = acc * (1.f - ms);
            float d = expf(log_depth[0]);
            d = fminf(fmaxf(d, 0.1f), 3.0f);
            g_dt = d / (float)(NT - 1);
        }
    }
}

__global__ void k_count(const int* __restrict__ ei) {
    int e = blockIdx.x * blockDim.x + threadIdx.x;
    if (e < NE) atomicAdd(&d_counts[ei[NE + e]], 1);
}

__global__ void k_scan() {
    __shared__ int sm[1024];
    int t = threadIdx.x;
    const int CH = (NN + 1023) / 1024;
    int beg = t * CH;
    int end = min(NN, beg + CH);
    int s = 0;
    for (int i = beg; i < end; i++) s += d_counts[i];
    sm[t] = s;
    __syncthreads();
    for (int o = 1; o < 1024; o <<= 1) {
        int v = (t >= o) ? sm[t - o] : 0;
        __syncthreads();
        sm[t] += v;
        __syncthreads();
    }
    int run = sm[t] - s;
    for (int i = beg; i < end; i++) {
        int c = d_counts[i];
        d_off[i] = run;
        d_cursor[i] = run;
        d_dis[i] = (c > 0) ? rsqrtf((float)c) : 0.f;
        run += c;
    }
    if (t == 1023) d_off[NN] = sm[1023];
}

__global__ void k_fill(const int* __restrict__ ei) {
    int e = blockIdx.x * blockDim.x + threadIdx.x;
    if (e < NE) {
        int c = ei[NE + e];
        int p = atomicAdd(&d_cursor[c], 1);
        d_csr_src[p] = ei[e];
    }
}

__global__ void k_split_w(const float* __restrict__ Wi, const float* __restrict__ gcn,
                          const float* __restrict__ gate, const float* __restrict__ Wo) {
    int i = blockIdx.x * blockDim.x + threadIdx.x;
    if (i >= WP_TOT) return;
    const float* src;
    int p;
    if (i < WP_GCN)       { src = Wi;   p = i - WP_I; }
    else if (i < WP_GATE) { src = gcn;  p = i - WP_GCN; }
    else if (i < WP_WO)   { src = gate; p = i - WP_GATE; }
    else                  { src = Wo;   p = i - WP_WO; }
    int c = p & 127;
    int k2 = p >> 7;
    float f0 = src[(2 * k2) * DH + c];
    float f1 = src[(2 * k2 + 1) * DH + c];
    uint32_t hi, lo;
    split_pack(f0, f1, hi, lo);
    d_whi[i] = hi;
    d_wlo[i] = lo;
}

// ---------------- GEMM building blocks --------------------------------------
__device__ __forceinline__ void stage_w_async(SmemC& s,
        const uint32_t* __restrict__ whi, const uint32_t* __restrict__ wlo,
        int kp0, int buf, int tid) {
#pragma unroll
    for (int it = 0; it < 2; it++) {
        int i = tid + it * 256;
        int kr = i >> 5, cq = i & 31;
        int gi = (kp0 + kr) * DH + cq * 4;
        cp16(smem_u32(&s.w[buf][0][kr * SW_STRIDE + cq * 4]), &whi[gi]);
        cp16(smem_u32(&s.w[buf][1][kr * SW_STRIDE + cq * 4]), &wlo[gi]);
    }
    cp_commit();
}

__device__ __forceinline__ void mma_phase(SmemC& s, int buf, float (&acc)[2][4][4],
                                          int wm, int wn, int grp, int qid) {
#pragma unroll
    for (int kk2 = 0; kk2 < 16; kk2 += 8) {
        uint32_t ah[2][4], al[2][4], bh[4][2], bl[4][2];
#pragma unroll
        for (int mi = 0; mi < 2; mi++) {
            int r = wm * 32 + mi * 16 + grp;
            int i0 = r * SA_STRIDE + kk2 + qid;
            int i1 = (r + 8) * SA_STRIDE + kk2 + qid;
            ah[mi][0] = s.a[0][i0];     ah[mi][1] = s.a[0][i1];
            ah[mi][2] = s.a[0][i0 + 4]; ah[mi][3] = s.a[0][i1 + 4];
            al[mi][0] = s.a[1][i0];     al[mi][1] = s.a[1][i1];
            al[mi][2] = s.a[1][i0 + 4]; al[mi][3] = s.a[1][i1 + 4];
        }
#pragma unroll
        for (int ni = 0; ni < 4; ni++) {
            int n = wn * 32 + ni * 8 + grp;
            bh[ni][0] = s.w[buf][0][(kk2 + qid) * SW_STRIDE + n];
            bh[ni][1] = s.w[buf][0][(kk2 + qid + 4) * SW_STRIDE + n];
            bl[ni][0] = s.w[buf][1][(kk2 + qid) * SW_STRIDE + n];
            bl[ni][1] = s.w[buf][1][(kk2 + qid + 4) * SW_STRIDE + n];
        }
#pragma unroll
        for (int mi = 0; mi < 2; mi++)
#pragma unroll
            for (int ni = 0; ni < 4; ni++) {
                mma_bf16(acc[mi][ni], al[mi], bh[ni]);
                mma_bf16(acc[mi][ni], ah[mi], bl[ni]);
                mma_bf16(acc[mi][ni], ah[mi], bh[ni]);
            }
    }
}

// ---------------- split-bf16 GEMM (cp.async W prefetch) ---------------------
// C[M x 128] = A[M x K] @ W[K x 128].
// EPI 0: C = acc + bias[col]
// EPI 2: C = LN(acc + bias) with (lg, lb); optional outT = fp16(dis_r * C)
template <int K, int EPI>
__global__ __launch_bounds__(256) void k_gemm_tc(
        const float* __restrict__ A,
        const uint32_t* __restrict__ whi, const uint32_t* __restrict__ wlo,
        const float* __restrict__ bias, float* __restrict__ C, int M,
        const float* __restrict__ lg, const float* __restrict__ lb,
        __half* __restrict__ outT) {
    __shared__ SmemC s;
    const int NC = K / 32;
    int tid = threadIdx.x;
    int warp = tid >> 5, lane = tid & 31;
    int grp = lane >> 2, qid = lane & 3;
    int wm = warp >> 2, wn = warp & 3;
    int r0 = blockIdx.x * 64;

    float acc[2][4][4];
#pragma unroll
    for (int mi = 0; mi < 2; mi++)
#pragma unroll
        for (int ni = 0; ni < 4; ni++)
#pragma unroll
            for (int j = 0; j < 4; j++) acc[mi][ni][j] = 0.f;

    stage_w_async(s, whi, wlo, 0, 0, tid);

    for (int c = 0; c < NC; c++) {
        int k0 = c * 32;
#pragma unroll
        for (int it = 0; it < 2; it++) {
            int i = tid + it * 256;
            int row = i >> 3, q = i & 7;
            int gr = r0 + row;
            float4 v = make_float4(0.f, 0.f, 0.f, 0.f);
            if (gr < M) v = *(const float4*)&A[gr * K + k0 + q * 4];
            uint32_t h0, l0, h1, l1;
            split_pack(v.x, v.y, h0, l0);
            split_pack(v.z, v.w, h1, l1);
            int base = row * SA_STRIDE + q * 2;
            s.a[0][base] = h0; s.a[0][base + 1] = h1;
            s.a[1][base] = l0; s.a[1][base + 1] = l1;
        }
        if (c + 1 < NC) {
            stage_w_async(s, whi, wlo, (c + 1) * 16, (c + 1) & 1, tid);
            cp_wait<1>();
        } else {
            cp_wait<0>();
        }
        __syncthreads();
        mma_phase(s, c & 1, acc, wm, wn, grp, qid);
        __syncthreads();
    }

    if (EPI == 0) {
#pragma unroll
        for (int mi = 0; mi < 2; mi++) {
            int row = r0 + wm * 32 + mi * 16 + grp;
#pragma unroll
            for (int half = 0; half < 2; half++) {
                int r = row + half * 8;
                if (r < M) {
#pragma unroll
                    for (int ni = 0; ni < 4; ni++) {
                        int col = wn * 32 + ni * 8 + 2 * qid;
                        C[r * DH + col]     = acc[mi][ni][half * 2 + 0] + bias[col];
                        C[r * DH + col + 1] = acc[mi][ni][half * 2 + 1] + bias[col + 1];
                    }
                }
            }
        }
    } else {
        // LN epilogue: stage tile (bias added) to smem, per-row warp LN
        float* tile = (float*)s.w;   // 64 x 132 floats (exact fit)
#pragma unroll
        for (int mi = 0; mi < 2; mi++) {
            int lrb = wm * 32 + mi * 16 + grp;
#pragma unroll
            for (int half = 0; half < 2; half++) {
                int lr = lrb + half * 8;
                if (r0 + lr < M) {
#pragma unroll
                    for (int ni = 0; ni < 4; ni++) {
                        int col = wn * 32 + ni * 8 + 2 * qid;
                        tile[lr * 132 + col]     = acc[mi][ni][half * 2 + 0] + bias[col];
                        tile[lr * 132 + col + 1] = acc[mi][ni][half * 2 + 1] + bias[col + 1];
                    }
                }
            }
        }
        __syncthreads();
        for (int i = 0; i < 8; i++) {
            int lr = warp * 8 + i;
            int r = r0 + lr;
            if (r >= M) break;
            float4 v = *(float4*)&tile[lr * 132 + lane * 4];
            float su = v.x + v.y + v.z + v.w;
            for (int o = 16; o > 0; o >>= 1) su += __shfl_xor_sync(0xffffffff, su, o);
            float mu = su * (1.f / 128.f);
            float dx = v.x - mu, dy = v.y - mu, dz = v.z - mu, dw = v.w - mu;
            float q = dx * dx + dy * dy + dz * dz + dw * dw;
            for (int o = 16; o > 0; o >>= 1) q += __shfl_xor_sync(0xffffffff, q, o);
            float rs = rsqrtf(q * (1.f / 128.f) + LNEPS);
            int c4 = lane * 4;
            float4 o4;
            o4.x = dx * rs * lg[c4 + 0] + lb[c4 + 0];
            o4.y = dy * rs * lg[c4 + 1] + lb[c4 + 1];
            o4.z = dz * rs * lg[c4 + 2] + lb[c4 + 2];
            o4.w = dw * rs * lg[c4 + 3] + lb[c4 + 3];
            *(float4*)&C[r * DH + c4] = o4;
            if (outT) {
                float di = d_dis[r];
                __half2 t0 = __floats2half2_rn(o4.x * di, o4.y * di);
                __half2 t1 = __floats2half2_rn(o4.z * di, o4.w * di);
                __half2* tp = (__half2*)&outT[r * DH + c4];
                tp[0] = t0; tp[1] = t1;
            }
        }
    }
}

// gate GEMM (K=256, A = concat(hc, hn)), cp.async W prefetch.
// FUSE 0: hc = blend;                         tout = fp16(dis*blend)
// FUSE 1: kv=tanh(blend)+rw*yin; y=h+ycoef*dt*kv; acc upd; tout = fp16(dis*y)
// FUSE 2: kv=tanh(blend)+rw*yin; h += dt/6*(acc+kv);       tout = fp16(dis*h)
template <int FUSE>
__global__ __launch_bounds__(256) void k_gate_tc(
        float* __restrict__ hc, const float* __restrict__ hn,
        const uint32_t* __restrict__ whi, const uint32_t* __restrict__ wlo,
        const float* __restrict__ gb, int M,
        const float* yin, float* yout,
        float* h, float* acc_buf,
        const float* __restrict__ res_w,
        float ycoef, float acoef, int first,
        __half* __restrict__ tout) {
    __shared__ SmemC s;
    const int NC = 8;
    int tid = threadIdx.x;
    int warp = tid >> 5, lane = tid & 31;
    int grp = lane >> 2, qid = lane & 3;
    int wm = warp >> 2, wn = warp & 3;
    int r0 = blockIdx.x * 64;

    float acc[2][4][4];
#pragma unroll
    for (int mi = 0; mi < 2; mi++)
#pragma unroll
        for (int ni = 0; ni < 4; ni++)
#pragma unroll
            for (int j = 0; j < 4; j++) acc[mi][ni][j] = 0.f;

    stage_w_async(s, whi, wlo, 0, 0, tid);

    for (int c = 0; c < NC; c++) {
        int k0 = c * 32;
#pragma unroll
        for (int it = 0; it < 2; it++) {
            int i = tid + it * 256;
            int row = i >> 3, q = i & 7;
            int gr = r0 + row;
            int cc = k0 + q * 4;
            float4 v = make_float4(0.f, 0.f, 0.f, 0.f);
            if (gr < M)
                v = (cc < DH) ? *(const float4*)&hc[gr * DH + cc]
                              : *(const float4*)&hn[gr * DH + (cc - DH)];
            uint32_t h0, l0, h1, l1;
            split_pack(v.x, v.y, h0, l0);
            split_pack(v.z, v.w, h1, l1);
            int base = row * SA_STRIDE + q * 2;
            s.a[0][base] = h0; s.a[0][base + 1] = h1;
            s.a[1][base] = l0; s.a[1][base + 1] = l1;
        }
        if (c + 1 < NC) {
            stage_w_async(s, whi, wlo, (c + 1) * 16, (c + 1) & 1, tid);
            cp_wait<1>();
        } else {
            cp_wait<0>();
        }
        __syncthreads();
        mma_phase(s, c & 1, acc, wm, wn, grp, qid);
        __syncthreads();
    }
    // all block-wide reads of hc complete (last __syncthreads above)
    float rw = (FUSE != 0) ? res_w[0] : 0.f;
    float dt = (FUSE != 0) ? g_dt : 0.f;
#pragma unroll
    for (int mi = 0; mi < 2; mi++) {
        int row = r0 + wm * 32 + mi * 16 + grp;
#pragma unroll
        for (int half = 0; half < 2; half++) {
            int r = row + half * 8;
            if (r < M) {
                float di = d_dis[r];
#pragma unroll
                for (int ni = 0; ni < 4; ni++) {
                    int col = wn * 32 + ni * 8 + 2 * qid;
                    float tv[2];
#pragma unroll
                    for (int j = 0; j < 2; j++) {
                        int c2 = col + j;
                        float z = acc[mi][ni][half * 2 + j] + gb[c2];
                        float gt = 1.f / (1.f + expf(-z));
                        int idx = r * DH + c2;
                        float blend = gt * hn[idx] + (1.f - gt) * hc[idx];
                        if (FUSE == 0) {
                            hc[idx] = blend;
                            tv[j] = blend;
                        } else if (FUSE == 1) {
                            float kv = tanhf(blend) + rw * yin[idx];
                            float yv = h[idx] + ycoef * dt * kv;
                            float av = first ? kv : acc_buf[idx] + acoef * kv;
                            yout[idx] = yv;
                            acc_buf[idx] = av;
                            tv[j] = yv;
                        } else {
                            float kv = tanhf(blend) + rw * yin[idx];
                            float hv = h[idx] + (dt * (1.f / 6.f)) * (acc_buf[idx] + kv);
                            h[idx] = hv;
                            tv[j] = hv;
                        }
                    }
                    *(__half2*)&tout[r * DH + col] =
                        __floats2half2_rn(tv[0] * di, tv[1] * di);
                }
            }
        }
    }
}

// ---------------- fp16 aggregation (warp per node, pure gather+sum) --------
// out[i] = dis_i * sum_{j in N(i)} t[j]   (t already carries dis_j)
__global__ void k_agg16(const __half* __restrict__ t, float* __restrict__ out) {
    int warp = threadIdx.x >> 5, lane = threadIdx.x & 31;
    int n = blockIdx.x * 8 + warp;
    if (n >= NN) return;
    int beg = d_off[n], end = d_off[n + 1];
    int c4 = lane * 4;
    float a0 = 0.f, a1 = 0.f, a2 = 0.f, a3 = 0.f;
    int e = beg;
    for (; e + 3 < end; e += 4) {
        int s0 = d_csr_src[e], s1 = d_csr_src[e + 1];
        int s2 = d_csr_src[e + 2], s3 = d_csr_src[e + 3];
        uint2 u0 = *(const uint2*)&t[s0 * DH + c4];
        uint2 u1 = *(const uint2*)&t[s1 * DH + c4];
        uint2 u2 = *(const uint2*)&t[s2 * DH + c4];
        uint2 u3 = *(const uint2*)&t[s3 * DH + c4];
        float2 f;
        f = __half22float2(*(__half2*)&u0.x); a0 += f.x; a1 += f.y;
        f = __half22float2(*(__half2*)&u0.y); a2 += f.x; a3 += f.y;
        f = __half22float2(*(__half2*)&u1.x); a0 += f.x; a1 += f.y;
        f = __half22float2(*(__half2*)&u1.y); a2 += f.x; a3 += f.y;
        f = __half22float2(*(__half2*)&u2.x); a0 += f.x; a1 += f.y;
        f = __half22float2(*(__half2*)&u2.y); a2 += f.x; a3 += f.y;
        f = __half22float2(*(__half2*)&u3.x); a0 += f.x; a1 += f.y;
        f = __half22float2(*(__half2*)&u3.y); a2 += f.x; a3 += f.y;
    }
    for (; e < end; e++) {
        int s0 = d_csr_src[e];
        uint2 u0 = *(const uint2*)&t[s0 * DH + c4];
        float2 f;
        f = __half22float2(*(__half2*)&u0.x); a0 += f.x; a1 += f.y;
        f = __half22float2(*(__half2*)&u0.y); a2 += f.x; a3 += f.y;
    }
    float di = d_dis[n];
    float4 v = make_float4(a0 * di, a1 * di, a2 * di, a3 * di);
    *(float4*)&out[n * DH + c4] = v;
}

// row LayerNorm (warp per row). MODE 1: + relu + *g_epi, optional fp16 dis out
template <int MODE>
__global__ void k_ln_rows(const float* __restrict__ in, const float* __restrict__ lg,
                          const float* __restrict__ lb, float* __restrict__ out, int M,
                          __half* __restrict__ tout) {
    int warp = threadIdx.x >> 5, lane = threadIdx.x & 31;
    int r = blockIdx.x * 4 + warp;
    if (r >= M) return;
    float4 v = *(const float4*)&in[r * DH + lane * 4];
    float s = v.x + v.y + v.z + v.w;
    for (int o = 16; o > 0; o >>= 1) s += __shfl_xor_sync(0xffffffff, s, o);
    float mu = s * (1.f / 128.f);
    float dx = v.x - mu, dy = v.y - mu, dz = v.z - mu, dw = v.w - mu;
    float q = dx * dx + dy * dy + dz * dz + dw * dw;
    for (int o = 16; o > 0; o >>= 1) q += __shfl_xor_sync(0xffffffff, q, o);
    float rs = rsqrtf(q * (1.f / 128.f) + LNEPS);
    float4 o4;
    float e = g_epi;
    int c = lane * 4;
    o4.x = dx * rs * lg[c + 0] + lb[c + 0];
    o4.y = dy * rs * lg[c + 1] + lb[c + 1];
    o4.z = dz * rs * lg[c + 2] + lb[c + 2];
    o4.w = dw * rs * lg[c + 3] + lb[c + 3];
    if (MODE == 1) {
        o4.x = fmaxf(o4.x, 0.f) * e;
        o4.y = fmaxf(o4.y, 0.f) * e;
        o4.z = fmaxf(o4.z, 0.f) * e;
        o4.w = fmaxf(o4.w, 0.f) * e;
    }
    *(float4*)&out[r * DH + c] = o4;
    if (MODE == 1 && tout) {
        float di = d_dis[r];
        __half2* tp = (__half2*)&tout[r * DH + c];
        tp[0] = __floats2half2_rn(o4.x * di, o4.y * di);
        tp[1] = __floats2half2_rn(o4.z * di, o4.w * di);
    }
}

// ---------------- output ---------------------------------------------------
__global__ void k_zero_out(float* out) {
    if (threadIdx.x < DH) out[threadIdx.x] = 0.f;
}

__global__ void k_colmean(const float* __restrict__ a, float* __restrict__ out) {
    int j = threadIdx.x;
    int r0 = blockIdx.x * 128;
    int r1 = min(NN, r0 + 128);
    float s = 0.f;
    for (int r = r0; r < r1; r++) s += a[r * DH + j];
    atomicAdd(&out[j], s * (1.f / (float)NN));
}

// ---------------- host orchestration ---------------------------------------
extern "C" void kernel_launch(void* const* d_in, const int* in_sizes, int n_in,
                              void* d_out, int out_size) {
    const float* x        = (const float*)d_in[0];
    const int*   ei       = (const int*)  d_in[1];
    const float* Wi       = (const float*)d_in[2];
    const float* bi       = (const float*)d_in[3];
    const float* ln_in_g  = (const float*)d_in[4];
    const float* ln_in_b  = (const float*)d_in[5];
    const float* meth     = (const float*)d_in[6];
    const float* hist     = (const float*)d_in[7];
    const float* gcn_w    = (const float*)d_in[8];
    const float* gcn_b    = (const float*)d_in[9];
    const float* ln_g     = (const float*)d_in[10];
    const float* ln_b     = (const float*)d_in[11];
    const float* gate_w   = (const float*)d_in[12];
    const float* gate_b   = (const float*)d_in[13];
    const float* res_w    = (const float*)d_in[14];
    const float* log_depth= (const float*)d_in[15];
    const float* Wo       = (const float*)d_in[16];
    const float* bo       = (const float*)d_in[17];
    const float* ln_out_g = (const float*)d_in[18];
    const float* ln_out_b = (const float*)d_in[19];
    float* out = (float*)d_out;

    float *p_g, *p_A, *p_B, *p_y, *p_acc, *p_h;
    __half* p_t;
    uint32_t *p_whi, *p_wlo;
    cudaGetSymbolAddress((void**)&p_g,   d_g);
    cudaGetSymbolAddress((void**)&p_A,   d_bufA);
    cudaGetSymbolAddress((void**)&p_B,   d_bufB);
    cudaGetSymbolAddress((void**)&p_y,   d_y);
    cudaGetSymbolAddress((void**)&p_acc, d_acc);
    cudaGetSymbolAddress((void**)&p_h,   d_h);
    cudaGetSymbolAddress((void**)&p_t,   d_t16);
    cudaGetSymbolAddress((void**)&p_whi, d_whi);
    cudaGetSymbolAddress((void**)&p_wlo, d_wlo);

    const int GEMM_GRID = (NN + 63) / 64;   // 313
    const int AGG_GRID  = (NN + 7) / 8;     // 2500
    const int LN_GRID   = (NN + 3) / 4;     // 5000

    const uint32_t* g0h = p_whi + WP_GCN;
    const uint32_t* g0l = p_wlo + WP_GCN;

    // prologue — launch index 3 = input-projection GEMM (ncu capture target)
    k_pre0<<<(NN + 255) / 256, 256>>>(log_depth, meth, hist);             // 0
    k_split_w<<<(WP_TOT + 255) / 256, 256>>>(Wi, gcn_w, gate_w, Wo);      // 1
    k_count<<<(NE + 255) / 256, 256>>>(ei);                               // 2
    k_gemm_tc<DIN, 0><<<GEMM_GRID, 256>>>(x, p_whi + WP_I, p_wlo + WP_I,
                                          bi, p_g, NN, nullptr, nullptr,
                                          nullptr);                       // 3
    k_scan<<<1, 1024>>>();                                                // 4
    k_fill<<<(NE + 255) / 256, 256>>>(ei);                                // 5
    // h = epi * relu(LN(x@Wi + bi)); t = fp16(dis * h)
    k_ln_rows<1><<<LN_GRID, 128>>>(p_g, ln_in_g, ln_in_b, p_h, NN, p_t);  // 6

    auto f_eval = [&](const float* yin, int mode, float ycoef, float acoef, int first) {
        // layer 0: agg(t) -> g; hc = LN(g@W0 + b0) -> A, t = dis*hc
        k_agg16<<<AGG_GRID, 256>>>(p_t, p_g);
        k_gemm_tc<DH, 2><<<GEMM_GRID, 256>>>(p_g, g0h, g0l, gcn_b, p_A, NN,
                                             ln_g, ln_b, p_t);
        // layer 1: agg(t) -> g; hn = LN(g@W1 + b1) -> B; gate -> A, t = dis*blend
        k_agg16<<<AGG_GRID, 256>>>(p_t, p_g);
        k_gemm_tc<DH, 2><<<GEMM_GRID, 256>>>(p_g, g0h + LAYER_P, g0l + LAYER_P,
                                             gcn_b + DH, p_B, NN,
                                             ln_g + DH, ln_b + DH, nullptr);
        k_gate_tc<0><<<GEMM_GRID, 256>>>(p_A, p_B, p_whi + WP_GATE, p_wlo + WP_GATE,
                                         gate_b, NN, nullptr, nullptr, nullptr,
                                         nullptr, nullptr, 0.f, 0.f, 0, p_t);
        // layer 2: agg(t) -> g; hn2 = LN(g@W2 + b2) -> B; gate2 + RK, t = dis*next
        k_agg16<<<AGG_GRID, 256>>>(p_t, p_g);
        k_gemm_tc<DH, 2><<<GEMM_GRID, 256>>>(p_g, g0h + 2 * LAYER_P, g0l + 2 * LAYER_P,
                                             gcn_b + 2 * DH, p_B, NN,
                                             ln_g + 2 * DH, ln_b + 2 * DH, nullptr);
        if (mode == 1)
            k_gate_tc<1><<<GEMM_GRID, 256>>>(p_A, p_B, p_whi + WP_GATE, p_wlo + WP_GATE,
                                             gate_b, NN, yin, p_y, p_h, p_acc,
                                             res_w, ycoef, acoef, first, p_t);
        else
            k_gate_tc<2><<<GEMM_GRID, 256>>>(p_A, p_B, p_whi + WP_GATE, p_wlo + WP_GATE,
                                             gate_b, NN, yin, nullptr, p_h, p_acc,
                                             res_w, 0.f, 0.f, 0, p_t);
    };

    for (int step = 0; step < NT - 1; step++) {
        f_eval(p_h, 1, 0.5f, 1.f, 1);   // k1
        f_eval(p_y, 1, 0.5f, 2.f, 0);   // k2
        f_eval(p_y, 1, 1.0f, 2.f, 0);   // k3
        f_eval(p_y, 2, 0.f, 0.f, 0);    // k4
    }

    // output projection + LN + global mean pool
    k_gemm_tc<DH, 0><<<GEMM_GRID, 256>>>(p_h, p_whi + WP_WO, p_wlo + WP_WO,
                                         bo, p_g, NN, nullptr, nullptr, nullptr);
    k_ln_rows<0><<<LN_GRID, 128>>>(p_g, ln_out_g, ln_out_b, p_B, NN, nullptr);
    k_zero_out<<<1, 128>>>(out);
    k_colmean<<<(NN + 127) / 128, 128>>>(p_B, out);
}